// round 3
// baseline (speedup 1.0000x reference)
#include <cuda_runtime.h>
#include <math.h>

#define T_MAXC 1000000
#define CHUNK 4096
#define NCHUNK ((T_MAXC + CHUNK - 1) / CHUNK)   // 245
#define THR 256
#define PER_THREAD (CHUNK / THR)                // 16

// Scratch (no allocations allowed — static device globals)
__device__ float  g_sumexp[T_MAXC];
__device__ float  g_evcnt[T_MAXC];
__device__ double g_chunk_sum[NCHUNK];
__device__ double g_chunk_off[NCHUNK];
__device__ double g_evx;
__device__ double g_logterm;

// ---------------------------------------------------------------------------
__global__ void zero_kernel() {
    int i = blockIdx.x * blockDim.x + threadIdx.x;
    if (i < T_MAXC) {
        g_sumexp[i] = 0.0f;
        g_evcnt[i]  = 0.0f;
    }
    if (i < NCHUNK) {
        g_chunk_sum[i] = 0.0;
        g_chunk_off[i] = 0.0;
    }
    if (i == 0) {
        g_evx = 0.0;
        g_logterm = 0.0;
    }
}

// ---------------------------------------------------------------------------
// Pass 1: histogram exp(x) and event counts by integer time; accumulate ev*x.
__global__ void accum_kernel(const float* __restrict__ x,
                             const float2* __restrict__ tgt, int n) {
    int stride = gridDim.x * blockDim.x;
    double evx = 0.0;
    for (int i = blockIdx.x * blockDim.x + threadIdx.x; i < n; i += stride) {
        float  xv = x[i];
        float2 te = tgt[i];          // .x = time, .y = event
        int ti = (int)te.x;
        ti = min(max(ti, 0), T_MAXC - 1);
        atomicAdd(&g_sumexp[ti], expf(xv));
        if (te.y != 0.0f) {
            atomicAdd(&g_evcnt[ti], te.y);
            evx += (double)te.y * (double)xv;
        }
    }
    // block reduce evx -> single atomic per block
    __shared__ double sh[THR];
    sh[threadIdx.x] = evx;
    __syncthreads();
    for (int s = THR / 2; s > 0; s >>= 1) {
        if (threadIdx.x < s) sh[threadIdx.x] += sh[threadIdx.x + s];
        __syncthreads();
    }
    if (threadIdx.x == 0) atomicAdd(&g_evx, sh[0]);
}

// ---------------------------------------------------------------------------
// Pass 2a: per-chunk sums of g_sumexp
__global__ void chunk_sum_kernel() {
    int b = blockIdx.x;
    int base = b * CHUNK + threadIdx.x * PER_THREAD;
    double s = 0.0;
#pragma unroll
    for (int j = 0; j < PER_THREAD; j++) {
        int idx = base + j;
        if (idx < T_MAXC) s += (double)g_sumexp[idx];
    }
    __shared__ double sh[THR];
    sh[threadIdx.x] = s;
    __syncthreads();
    for (int st = THR / 2; st > 0; st >>= 1) {
        if (threadIdx.x < st) sh[threadIdx.x] += sh[threadIdx.x + st];
        __syncthreads();
    }
    if (threadIdx.x == 0) g_chunk_sum[b] = sh[0];
}

// Pass 2b: exclusive suffix scan over the (245) chunk sums — trivial size.
__global__ void chunk_offset_kernel() {
    if (threadIdx.x == 0 && blockIdx.x == 0) {
        double run = 0.0;
        for (int b = NCHUNK - 1; b >= 0; b--) {
            g_chunk_off[b] = run;
            run += g_chunk_sum[b];
        }
    }
}

// Pass 2c: within-chunk suffix scan; accumulate evcnt[t] * log(cum[t]).
__global__ void logterm_kernel() {
    int b = blockIdx.x;
    int tid = threadIdx.x;
    int base = b * CHUNK + tid * PER_THREAD;

    // per-thread local sum
    double local = 0.0;
#pragma unroll
    for (int j = 0; j < PER_THREAD; j++) {
        int idx = base + j;
        if (idx < T_MAXC) local += (double)g_sumexp[idx];
    }

    // inclusive suffix scan over thread-local sums (Hillis-Steele)
    __shared__ double sh[THR];
    sh[tid] = local;
    __syncthreads();
    for (int s = 1; s < THR; s <<= 1) {
        double v = (tid + s < THR) ? sh[tid + s] : 0.0;
        __syncthreads();
        sh[tid] += v;
        __syncthreads();
    }
    double offset = g_chunk_off[b] + sh[tid] - local;  // exclusive suffix from right

    // walk own 16 buckets right-to-left
    double run = offset;
    double contrib = 0.0;
#pragma unroll
    for (int j = PER_THREAD - 1; j >= 0; j--) {
        int idx = base + j;
        if (idx < T_MAXC) {
            run += (double)g_sumexp[idx];
            float ec = g_evcnt[idx];
            if (ec > 0.0f) {
                contrib += (double)ec * (double)logf((float)run);
            }
        }
    }

    // block reduce contrib
    __syncthreads();
    sh[tid] = contrib;
    __syncthreads();
    for (int st = THR / 2; st > 0; st >>= 1) {
        if (tid < st) sh[tid] += sh[tid + st];
        __syncthreads();
    }
    if (tid == 0) atomicAdd(&g_logterm, sh[0]);
}

// ---------------------------------------------------------------------------
__global__ void finalize_kernel(float* out, int n) {
    if (threadIdx.x == 0 && blockIdx.x == 0) {
        double loss = g_logterm - g_evx;
        out[0] = (float)sqrt(loss / (double)n);
    }
}

// ---------------------------------------------------------------------------
extern "C" void kernel_launch(void* const* d_in, const int* in_sizes, int n_in,
                              void* d_out, int out_size) {
    const float*  x   = (const float*)d_in[0];
    const float2* tgt = (const float2*)d_in[1];
    float* out = (float*)d_out;
    int n = in_sizes[0];

    int zgrid = (T_MAXC + THR - 1) / THR;
    zero_kernel<<<zgrid, THR>>>();

    int ablocks = 1184;  // ~8 blocks/SM grid-stride
    accum_kernel<<<ablocks, THR>>>(x, tgt, n);

    chunk_sum_kernel<<<NCHUNK, THR>>>();
    chunk_offset_kernel<<<1, 32>>>();
    logterm_kernel<<<NCHUNK, THR>>>();

    finalize_kernel<<<1, 32>>>(out, n);
}

// round 4
// speedup vs baseline: 1.0962x; 1.0962x over previous
#include <cuda_runtime.h>
#include <math.h>

#define T_MAXC 1000000
#define CHUNK 4096
#define NCHUNK ((T_MAXC + CHUNK - 1) / CHUNK)   // 245
#define THR 256
#define PER_THREAD (CHUNK / THR)                // 16
#define FP_SCALE 1073741824.0                   // 2^30
#define INV_FP_SCALE (1.0 / 1073741824.0)
#define LOW_MASK ((1ULL << 48) - 1ULL)

// Scratch (no allocations allowed — static device globals)
// Packed histogram: low 48 bits = sum(exp(x)) in 2^-30 fixed point,
// high 16 bits = event count. One atomicAdd per element covers both.
__device__ unsigned long long g_packed[T_MAXC];
__device__ double g_chunk_sum[NCHUNK];
__device__ double g_chunk_off[NCHUNK];
__device__ double g_evx;
__device__ double g_logterm;
__device__ unsigned int g_c1;
__device__ unsigned int g_c2;

// ---------------------------------------------------------------------------
__global__ void zero_kernel() {
    int i = blockIdx.x * blockDim.x + threadIdx.x;
    ulonglong2* p = reinterpret_cast<ulonglong2*>(g_packed);
    if (i < T_MAXC / 2) p[i] = make_ulonglong2(0ULL, 0ULL);
    if (i == 0) {
        g_evx = 0.0;
        g_logterm = 0.0;
        g_c1 = 0u;
        g_c2 = 0u;
    }
}

// ---------------------------------------------------------------------------
// Pass 1: single packed u64 atomic per element + block-reduced ev*x.
__device__ __forceinline__ void process_elem(float xv, float tv, float ev,
                                             double& evx) {
    int ti = (int)tv;
    ti = min(max(ti, 0), T_MAXC - 1);
    unsigned long long enc =
        (unsigned long long)((double)expf(xv) * FP_SCALE);
    if (ev != 0.0f) {
        enc |= (1ULL << 48);
        evx += (double)xv;
    }
    atomicAdd(&g_packed[ti], enc);
}

__global__ void accum_kernel(const float* __restrict__ x,
                             const float* __restrict__ tgt, int n) {
    int n4 = n >> 2;
    const float4* x4 = reinterpret_cast<const float4*>(x);
    const float4* t4 = reinterpret_cast<const float4*>(tgt);
    int stride = gridDim.x * blockDim.x;
    double evx = 0.0;

    for (int i = blockIdx.x * blockDim.x + threadIdx.x; i < n4; i += stride) {
        float4 xv = x4[i];
        float4 ta = t4[2 * i];       // (t0,e0,t1,e1)
        float4 tb = t4[2 * i + 1];   // (t2,e2,t3,e3)
        process_elem(xv.x, ta.x, ta.y, evx);
        process_elem(xv.y, ta.z, ta.w, evx);
        process_elem(xv.z, tb.x, tb.y, evx);
        process_elem(xv.w, tb.z, tb.w, evx);
    }
    // scalar tail (n not multiple of 4)
    if (blockIdx.x == 0 && threadIdx.x == 0) {
        for (int i = n4 * 4; i < n; i++)
            process_elem(x[i], tgt[2 * i], tgt[2 * i + 1], evx);
    }

    // block reduce evx -> single atomic per block
    __shared__ double sh[THR];
    sh[threadIdx.x] = evx;
    __syncthreads();
    for (int s = THR / 2; s > 0; s >>= 1) {
        if (threadIdx.x < s) sh[threadIdx.x] += sh[threadIdx.x + s];
        __syncthreads();
    }
    if (threadIdx.x == 0) atomicAdd(&g_evx, sh[0]);
}

// ---------------------------------------------------------------------------
// Pass 2a: per-chunk sums; the LAST block to finish also does the 245-entry
// suffix scan in parallel (no serial single-thread kernel).
__global__ void chunk_scan_kernel() {
    int b = blockIdx.x;
    int tid = threadIdx.x;
    int base = b * CHUNK + tid * PER_THREAD;

    double s = 0.0;
#pragma unroll
    for (int j = 0; j < PER_THREAD; j++) {
        int idx = base + j;
        if (idx < T_MAXC) s += (double)(g_packed[idx] & LOW_MASK);
    }
    s *= INV_FP_SCALE;

    __shared__ double sh[THR];
    sh[tid] = s;
    __syncthreads();
    for (int st = THR / 2; st > 0; st >>= 1) {
        if (tid < st) sh[tid] += sh[tid + st];
        __syncthreads();
    }
    if (tid == 0) g_chunk_sum[b] = sh[0];
    __threadfence();

    __shared__ bool is_last;
    if (tid == 0) {
        unsigned int old = atomicAdd(&g_c1, 1u);
        is_last = (old == gridDim.x - 1);
    }
    __syncthreads();

    if (is_last) {
        // exclusive suffix scan over NCHUNK chunk sums (Hillis-Steele)
        double v = (tid < NCHUNK) ? g_chunk_sum[tid] : 0.0;
        sh[tid] = v;
        __syncthreads();
        for (int st = 1; st < THR; st <<= 1) {
            double add = (tid + st < THR) ? sh[tid + st] : 0.0;
            __syncthreads();
            sh[tid] += add;
            __syncthreads();
        }
        if (tid < NCHUNK) g_chunk_off[tid] = sh[tid] - v;
    }
}

// ---------------------------------------------------------------------------
// Pass 2b: within-chunk suffix scan + evcnt*log(cum); LAST block finalizes.
__global__ void logterm_kernel(float* __restrict__ out, int n) {
    int b = blockIdx.x;
    int tid = threadIdx.x;
    int base = b * CHUNK + tid * PER_THREAD;

    unsigned long long pk[PER_THREAD];
    double se[PER_THREAD];
    double local = 0.0;
#pragma unroll
    for (int j = 0; j < PER_THREAD; j++) {
        int idx = base + j;
        pk[j] = (idx < T_MAXC) ? g_packed[idx] : 0ULL;
        se[j] = (double)(pk[j] & LOW_MASK) * INV_FP_SCALE;
        local += se[j];
    }

    // inclusive suffix scan over thread-local sums
    __shared__ double sh[THR];
    sh[tid] = local;
    __syncthreads();
    for (int s = 1; s < THR; s <<= 1) {
        double v = (tid + s < THR) ? sh[tid + s] : 0.0;
        __syncthreads();
        sh[tid] += v;
        __syncthreads();
    }
    double run = g_chunk_off[b] + sh[tid] - local;  // exclusive suffix

    double contrib = 0.0;
#pragma unroll
    for (int j = PER_THREAD - 1; j >= 0; j--) {
        run += se[j];
        unsigned int cnt = (unsigned int)(pk[j] >> 48);
        if (cnt != 0u) {
            contrib += (double)cnt * (double)logf((float)run);
        }
    }

    __syncthreads();
    sh[tid] = contrib;
    __syncthreads();
    for (int st = THR / 2; st > 0; st >>= 1) {
        if (tid < st) sh[tid] += sh[tid + st];
        __syncthreads();
    }
    __shared__ bool is_last;
    if (tid == 0) {
        atomicAdd(&g_logterm, sh[0]);
        __threadfence();
        unsigned int old = atomicAdd(&g_c2, 1u);
        is_last = (old == gridDim.x - 1);
    }
    __syncthreads();

    if (is_last && tid == 0) {
        double loss = g_logterm - g_evx;
        out[0] = (float)sqrt(loss / (double)n);
    }
}

// ---------------------------------------------------------------------------
extern "C" void kernel_launch(void* const* d_in, const int* in_sizes, int n_in,
                              void* d_out, int out_size) {
    const float* x   = (const float*)d_in[0];
    const float* tgt = (const float*)d_in[1];
    float* out = (float*)d_out;
    int n = in_sizes[0];

    int zgrid = (T_MAXC / 2 + THR - 1) / THR;
    zero_kernel<<<zgrid, THR>>>();

    accum_kernel<<<1184, THR>>>(x, tgt, n);

    chunk_scan_kernel<<<NCHUNK, THR>>>();
    logterm_kernel<<<NCHUNK, THR>>>(out, n);
}

// round 6
// speedup vs baseline: 1.9960x; 1.8209x over previous
#include <cuda_runtime.h>
#include <math.h>

#define T_MAXC 1000000
#define CHUNK 1024
#define NCHUNK 977                         // ceil(1e6 / 1024)
#define T_PAD (NCHUNK * CHUNK)             // 1000448 (padding buckets stay 0)
#define THR 256
#define FPS 2048.0f                        // 2^11 fixed-point scale
#define INV_FPS_F (1.0f / 2048.0f)
#define EMASK 0x00FFFFFFu

typedef unsigned long long u64;
typedef unsigned int u32;

// Scratch (static device globals; no allocation allowed)
// Packed bucket: bits[0:24) = sum(exp(x)) in 2^-11 fixed point, bits[24:32) = event count.
__device__ u32 g_packed[T_PAD];
__device__ u64 g_chunk_sum[1024];          // exact integer chunk sums (977 used, rest 0)
__device__ u64 g_chunk_off[1024];          // exclusive suffix sums (integer)
__device__ double g_evx;
__device__ double g_logterm;
__device__ u32 g_c1;
__device__ u32 g_c2;

// ---------------------------------------------------------------------------
// shuffle-scan helpers
__device__ __forceinline__ u64 warp_suffix_incl(u64 v) {
    int lane = threadIdx.x & 31;
#pragma unroll
    for (int s = 1; s < 32; s <<= 1) {
        u64 o = __shfl_down_sync(0xFFFFFFFFu, v, s);
        if (lane + s < 32) v += o;
    }
    return v;
}

// exclusive suffix (sum over threads with larger tid); one __syncthreads inside
__device__ __forceinline__ u64 block_suffix_excl(u64 local, u64* shw) {
    int lane = threadIdx.x & 31, wid = threadIdx.x >> 5;
    u64 v = warp_suffix_incl(local);
    if (lane == 0) shw[wid] = v;
    __syncthreads();
    u64 ws = 0;
#pragma unroll
    for (int w = 0; w < THR / 32; w++)
        if (w > wid) ws += shw[w];
    return (v - local) + ws;
}

__device__ __forceinline__ u64 block_reduce_u64(u64 v, u64* shw) {
    int lane = threadIdx.x & 31, wid = threadIdx.x >> 5;
#pragma unroll
    for (int s = 16; s > 0; s >>= 1) v += __shfl_down_sync(0xFFFFFFFFu, v, s);
    if (lane == 0) shw[wid] = v;
    __syncthreads();
    u64 t = 0;
    if (threadIdx.x == 0)
#pragma unroll
        for (int w = 0; w < THR / 32; w++) t += shw[w];
    return t;  // valid on tid 0
}

__device__ __forceinline__ double block_reduce_f64(double v, double* shw) {
    int lane = threadIdx.x & 31, wid = threadIdx.x >> 5;
#pragma unroll
    for (int s = 16; s > 0; s >>= 1) v += __shfl_down_sync(0xFFFFFFFFu, v, s);
    if (lane == 0) shw[wid] = v;
    __syncthreads();
    double t = 0.0;
    if (threadIdx.x == 0)
#pragma unroll
        for (int w = 0; w < THR / 32; w++) t += shw[w];
    return t;  // valid on tid 0
}

// ---------------------------------------------------------------------------
__global__ void zero_kernel() {
    int i = blockIdx.x * blockDim.x + threadIdx.x;      // 977*256 = 250112 = T_PAD/4
    reinterpret_cast<uint4*>(g_packed)[i] = make_uint4(0u, 0u, 0u, 0u);
    if (i < 1024) { g_chunk_sum[i] = 0ULL; g_chunk_off[i] = 0ULL; }
    if (i == 0) { g_evx = 0.0; g_logterm = 0.0; g_c1 = 0u; g_c2 = 0u; }
}

// ---------------------------------------------------------------------------
// Pass 1: one u32 atomic per element (sumexp fixed-point + event count packed).
__device__ __forceinline__ void proc(float xv, float tv, float ev, double& evx) {
    int ti = (int)tv;
    ti = min(max(ti, 0), T_MAXC - 1);
    u32 enc = __float2uint_rn(expf(xv) * FPS) + ((u32)ev << 24);
    atomicAdd(&g_packed[ti], enc);
    if (ev != 0.0f) evx += (double)xv;
}

__global__ void __launch_bounds__(THR) accum_kernel(const float* __restrict__ x,
                                                    const float* __restrict__ tgt,
                                                    int n) {
    const float4* x4 = reinterpret_cast<const float4*>(x);
    const float4* t4 = reinterpret_cast<const float4*>(tgt);
    int n4 = n >> 2;
    int stride = gridDim.x * blockDim.x;
    double evx = 0.0;

    for (int i = blockIdx.x * blockDim.x + threadIdx.x; i < n4; i += stride) {
        float4 xv = x4[i];
        float4 ta = t4[2 * i];       // (t0,e0,t1,e1)
        float4 tb = t4[2 * i + 1];   // (t2,e2,t3,e3)
        proc(xv.x, ta.x, ta.y, evx);
        proc(xv.y, ta.z, ta.w, evx);
        proc(xv.z, tb.x, tb.y, evx);
        proc(xv.w, tb.z, tb.w, evx);
    }
    if (blockIdx.x == 0 && threadIdx.x == 0) {           // scalar tail
        for (int i = n4 * 4; i < n; i++)
            proc(x[i], tgt[2 * i], tgt[2 * i + 1], evx);
    }

    __shared__ double shd[THR / 32];
    double t = block_reduce_f64(evx, shd);
    if (threadIdx.x == 0) atomicAdd(&g_evx, t);
}

// ---------------------------------------------------------------------------
// Pass 2a: exact integer per-chunk sums; last block does the 977-entry suffix scan.
__global__ void __launch_bounds__(THR) chunk_scan_kernel() {
    __shared__ u64 shw[THR / 32];
    int b = blockIdx.x, tid = threadIdx.x;

    uint4 v = reinterpret_cast<const uint4*>(g_packed)[b * (CHUNK / 4) + tid];
    u64 s = (u64)((v.x & EMASK) + (v.y & EMASK) + (v.z & EMASK) + (v.w & EMASK));

    u64 tot = block_reduce_u64(s, shw);
    __shared__ bool is_last;
    if (tid == 0) {
        g_chunk_sum[b] = tot;
        __threadfence();
        is_last = (atomicAdd(&g_c1, 1u) == gridDim.x - 1);
    }
    __syncthreads();

    if (is_last) {
        volatile u64* vs = g_chunk_sum;
        u64 ls[4];
        u64 local = 0;
#pragma unroll
        for (int j = 0; j < 4; j++) { ls[j] = vs[tid * 4 + j]; local += ls[j]; }
        u64 run = block_suffix_excl(local, shw);
#pragma unroll
        for (int j = 3; j >= 0; j--) {
            g_chunk_off[tid * 4 + j] = run;
            run += ls[j];
        }
    }
}

// ---------------------------------------------------------------------------
// Pass 2b: within-chunk integer suffix scan + evcnt*log(cum); last block finalizes.
__global__ void __launch_bounds__(THR) logterm_kernel(float* __restrict__ out, int n) {
    __shared__ u64 shw[THR / 32];
    __shared__ double shd[THR / 32];
    int b = blockIdx.x, tid = threadIdx.x;

    uint4 v = reinterpret_cast<const uint4*>(g_packed)[b * (CHUNK / 4) + tid];
    u32 e0 = v.x & EMASK, e1 = v.y & EMASK, e2 = v.z & EMASK, e3 = v.w & EMASK;
    u32 c0 = v.x >> 24,  c1 = v.y >> 24,  c2 = v.z >> 24,  c3 = v.w >> 24;

    u64 local = (u64)(e0 + e1 + e2 + e3);
    u64 run = block_suffix_excl(local, shw) + g_chunk_off[b];

    double contrib = 0.0;
    run += e3; if (c3) contrib += (double)c3 * (double)logf(__ull2float_rn(run) * INV_FPS_F);
    run += e2; if (c2) contrib += (double)c2 * (double)logf(__ull2float_rn(run) * INV_FPS_F);
    run += e1; if (c1) contrib += (double)c1 * (double)logf(__ull2float_rn(run) * INV_FPS_F);
    run += e0; if (c0) contrib += (double)c0 * (double)logf(__ull2float_rn(run) * INV_FPS_F);

    __syncthreads();  // shw/shd reuse barrier
    double t = block_reduce_f64(contrib, shd);

    __shared__ bool is_last;
    if (tid == 0) {
        atomicAdd(&g_logterm, t);
        __threadfence();
        is_last = (atomicAdd(&g_c2, 1u) == gridDim.x - 1);
    }
    __syncthreads();

    if (is_last && tid == 0) {
        double loss = *((volatile double*)&g_logterm) - *((volatile double*)&g_evx);
        out[0] = (float)sqrt(loss / (double)n);
    }
}

// ---------------------------------------------------------------------------
extern "C" void kernel_launch(void* const* d_in, const int* in_sizes, int n_in,
                              void* d_out, int out_size) {
    const float* x   = (const float*)d_in[0];
    const float* tgt = (const float*)d_in[1];
    float* out = (float*)d_out;
    int n = in_sizes[0];

    zero_kernel<<<NCHUNK, THR>>>();                 // 977*256 threads == T_PAD/4
    accum_kernel<<<1184, THR>>>(x, tgt, n);
    chunk_scan_kernel<<<NCHUNK, THR>>>();
    logterm_kernel<<<NCHUNK, THR>>>(out, n);
}